// round 4
// baseline (speedup 1.0000x reference)
#include <cuda_runtime.h>
#include <cstdint>

// Dims: N=32, K=32, T=128, H=768
#define NN 32
#define KK 32
#define TT 128
#define HH 768
#define H2 1536

// Output layout (float32 concat)
#define OFF_SCORE 0
#define OFF_ENC   1024
#define OFF_MASK  (1024 + 3145728)
#define OFF_USE   (OFF_MASK + 4096)
#define OFF_IDX   (OFF_USE + 24576)

// Scratch
__device__ float g_cqk[NN * HH];   // cqk_pro [n][g] (bias folded)
__device__ float g_v[NN * HH];     // v [n][h]
__device__ float g_c[NN];          // b_k . cqk_pro[n]

// kernel-1 grid layout
#define KA_BLOCKS 96
#define PF_BLOCKS 16
#define KD_ITEMS  (786432 + 6144 + 4096 + 4096)   // 800768
#define KD_BLOCKS ((KD_ITEMS + 255) / 256)        // 3128
#define K1_BLOCKS (KA_BLOCKS + PF_BLOCKS + KD_BLOCKS)

// ---------------------------------------------------------------------------
// Kernel 1: fused  [kA GEMM | L2 prefetch | kD gather]
//   kA: cqk_pro[n,g] = b_cqk[g] + sum_t X[n,t] * W_cqk[g,t],  X=[ctx[:,2,:],tracked]
//       96 blocks x 8 g-rows; thread=(g=warp, n=lane); W read ONCE total.
// ---------------------------------------------------------------------------
__global__ void __launch_bounds__(256) k1_fused(
    const float* __restrict__ ctx,      // (N,3,H)
    const float* __restrict__ tracked,  // (N,H)
    const float* __restrict__ W_cqk,    // (H,2H)
    const float* __restrict__ b_cqk,    // (H,)
    const float* __restrict__ p0,       // (N,K,T,H)
    const float* __restrict__ p1,       // (N,K,H)
    const int*   __restrict__ pmask,    // (N,K,T) bool-as-int32
    const int*   __restrict__ label,    // (N,)
    const int*   __restrict__ ptok,     // (N,K,T)
    const float* __restrict__ W_k,      // (H,H)
    float* __restrict__ out)
{
    int blk = blockIdx.x;
    int tid = threadIdx.x;

    if (blk < KA_BLOCKS) {
        // ---- kA ----
        __shared__ float4 Xs[32 * 33];          // [tt4][n], padded stride 33
        int w    = tid >> 5;
        int lane = tid & 31;
        int g    = blk * 8 + w;
        const float4* Wrow = reinterpret_cast<const float4*>(W_cqk + (size_t)g * H2);

        int fn = tid >> 3;                      // fill: n
        int fj = tid & 7;                       // fill: f4 group
        const float4* ctx4 = reinterpret_cast<const float4*>(ctx + ((size_t)fn * 3 + 2) * HH);
        const float4* trk4 = reinterpret_cast<const float4*>(tracked + (size_t)fn * HH);

        float acc = 0.f;
        for (int ch = 0; ch < 12; ++ch) {
            const float4* src4 = (ch < 6) ? (ctx4 + ch * 32) : (trk4 + (ch - 6) * 32);
            __syncthreads();
#pragma unroll
            for (int m = 0; m < 4; ++m) {
                int tt4 = fj + 8 * m;
                Xs[tt4 * 33 + fn] = src4[tt4];
            }
            __syncthreads();
            const float4* Wc = Wrow + ch * 32;
#pragma unroll 8
            for (int tt4 = 0; tt4 < 32; ++tt4) {
                float4 wv = Wc[tt4];
                float4 xv = Xs[tt4 * 33 + lane];
                acc = fmaf(wv.x, xv.x, acc); acc = fmaf(wv.y, xv.y, acc);
                acc = fmaf(wv.z, xv.z, acc); acc = fmaf(wv.w, xv.w, acc);
            }
        }
        g_cqk[lane * HH + g] = acc + __ldg(b_cqk + g);
        return;
    }

    if (blk < KA_BLOCKS + PF_BLOCKS) {
        // ---- L2 prefetch of p1 (24576 lines) and W_k (18432 lines) ----
        int pidx = (blk - KA_BLOCKS) * 256 + tid;
        const char* b1 = (const char*)p1;
        const char* b2 = (const char*)W_k;
        for (int i = pidx; i < 24576; i += PF_BLOCKS * 256)
            asm volatile("prefetch.global.L2 [%0];" :: "l"(b1 + (size_t)i * 128));
        for (int i = pidx; i < 18432; i += PF_BLOCKS * 256)
            asm volatile("prefetch.global.L2 [%0];" :: "l"(b2 + (size_t)i * 128));
        return;
    }

    // ---- kD gather ----
    int idx = (blk - KA_BLOCKS - PF_BLOCKS) * 256 + tid;
    const int ENC_F4 = NN * TT * HH / 4;        // 786432
    const int USE_F4 = NN * HH / 4;             // 6144
    const int MT     = NN * TT;                 // 4096

    if (idx < ENC_F4) {
        int per_n = TT * HH / 4;                // 24576
        int n = idx / per_n;
        int r = idx - n * per_n;
        int lab = __ldg(label + n);
        const float4* src = reinterpret_cast<const float4*>(
            p0 + ((size_t)(n * KK + lab)) * TT * HH);
        float4* dst = reinterpret_cast<float4*>(out + OFF_ENC + (size_t)n * TT * HH);
        dst[r] = src[r];
        return;
    }
    idx -= ENC_F4;
    if (idx < USE_F4) {
        int per_n = HH / 4;                     // 192
        int n = idx / per_n;
        int r = idx - n * per_n;
        int lab = __ldg(label + n);
        const float4* src = reinterpret_cast<const float4*>(
            p1 + ((size_t)(n * KK + lab)) * HH);
        float4* dst = reinterpret_cast<float4*>(out + OFF_USE + (size_t)n * HH);
        dst[r] = src[r];
        return;
    }
    idx -= USE_F4;
    if (idx < MT) {
        int n = idx / TT;
        int t = idx - n * TT;
        int lab = __ldg(label + n);
        out[OFF_MASK + idx] = (pmask[((size_t)(n * KK + lab)) * TT + t] != 0) ? 1.0f : 0.0f;
        return;
    }
    idx -= MT;
    if (idx < MT) {
        int n = idx / TT;
        int t = idx - n * TT;
        int lab = __ldg(label + n);
        out[OFF_IDX + idx] = (float)ptok[((size_t)(n * KK + lab)) * TT + t];
        return;
    }
}

// ---------------------------------------------------------------------------
// Kernel 2 (kB): v[n,h] = sum_g cqk[n,g] * W_k[g,h];  c[n] = b_k . cqk[n,:]
//   96 blocks x 8 h; thread = (hf4 = tid&1, n = (tid>>1)&31, gseg = tid>>6).
//   W_k read exactly once (h-tiles partition). cqk staged in smem g-chunks.
// ---------------------------------------------------------------------------
#define GCH 256
__global__ void __launch_bounds__(256) k2_v(
    const float* __restrict__ W_k,   // (H,H)
    const float* __restrict__ b_k)   // (H,)
{
    __shared__ float sc[GCH * 33];              // [gl][n], padded stride 33 (33.8 KB)
    __shared__ float4 red[4 * 64];              // gseg partials
    __shared__ float red2[8 * 32];              // c partials (block 0)

    int tid  = threadIdx.x;
    int hf4  = tid & 1;
    int n    = (tid >> 1) & 31;
    int gseg = tid >> 6;
    int h    = blockIdx.x * 8 + hf4 * 4;

    // c-role mapping (block 0)
    int cn   = tid & 31;
    int cseg = tid >> 5;                        // 8 segments of 32 g per chunk

    float4 acc = make_float4(0.f, 0.f, 0.f, 0.f);
    float cacc = 0.f;

    for (int ch = 0; ch < 3; ++ch) {
        __syncthreads();
        // fill sc: 8192 elems, coalesced read of g_cqk[n][g]
        for (int s = tid; s < NN * GCH; s += 256) {
            int nf = s >> 8;                    // s / 256
            int gl = s & 255;
            sc[gl * 33 + nf] = g_cqk[nf * HH + ch * GCH + gl];
        }
        __syncthreads();

        int g0 = ch * GCH;
#pragma unroll 4
        for (int i = 0; i < 64; ++i) {
            int gl = gseg * 64 + i;
            float4 wv = __ldg(reinterpret_cast<const float4*>(
                W_k + (size_t)(g0 + gl) * HH + h));
            float x = sc[gl * 33 + n];
            acc.x = fmaf(wv.x, x, acc.x); acc.y = fmaf(wv.y, x, acc.y);
            acc.z = fmaf(wv.z, x, acc.z); acc.w = fmaf(wv.w, x, acc.w);
        }
        if (blockIdx.x == 0) {
            for (int i = 0; i < 32; ++i) {
                int gl = cseg * 32 + i;
                cacc = fmaf(__ldg(b_k + g0 + gl), sc[gl * 33 + cn], cacc);
            }
        }
    }
    __syncthreads();

    red[gseg * 64 + (tid & 63)] = acc;
    if (blockIdx.x == 0) red2[cseg * 32 + cn] = cacc;
    __syncthreads();

    if (gseg == 0) {
        float4 a = red[tid & 63];
        float4 b = red[64 + (tid & 63)];
        float4 c = red[128 + (tid & 63)];
        float4 d = red[192 + (tid & 63)];
        float4 v = make_float4(a.x + b.x + c.x + d.x, a.y + b.y + c.y + d.y,
                               a.z + b.z + c.z + d.z, a.w + b.w + c.w + d.w);
        *reinterpret_cast<float4*>(g_v + (size_t)n * HH + h) = v;
    }
    if (blockIdx.x == 0 && tid < 32) {
        float s = 0.f;
#pragma unroll
        for (int j = 0; j < 8; ++j) s += red2[j * 32 + tid];
        g_c[tid] = s;
    }
}

// ---------------------------------------------------------------------------
// Kernel 3 (kC): score[n,k] = p1[n,k,:].v[n,:] + c[n], masked. Warp per (n,k).
// p1 is L2-resident (prefetched in kernel 1).
// ---------------------------------------------------------------------------
__global__ void __launch_bounds__(256) k3_score(
    const float* __restrict__ p1,        // (N,K,H)
    const int* __restrict__ ck_mask,     // (N,K) bool-as-int32
    float* __restrict__ out)
{
    int wid  = blockIdx.x * 8 + (threadIdx.x >> 5);
    int lane = threadIdx.x & 31;
    int n = wid / KK;
    int k = wid - n * KK;

    const float4* p4 = reinterpret_cast<const float4*>(p1 + ((size_t)n * KK + k) * HH);
    const float4* v4 = reinterpret_cast<const float4*>(g_v + (size_t)n * HH);

    float s = 0.f;
#pragma unroll
    for (int j = lane; j < 192; j += 32) {
        float4 a = p4[j];
        float4 b = v4[j];
        s = fmaf(a.x, b.x, s); s = fmaf(a.y, b.y, s);
        s = fmaf(a.z, b.z, s); s = fmaf(a.w, b.w, s);
    }
#pragma unroll
    for (int o = 16; o > 0; o >>= 1) s += __shfl_down_sync(0xffffffffu, s, o);
    if (lane == 0) {
        s += g_c[n];
        if (ck_mask[n * KK + k] == 0) s = -1e20f;
        out[OFF_SCORE + n * KK + k] = s;
    }
}

extern "C" void kernel_launch(void* const* d_in, const int* in_sizes, int n_in,
                              void* d_out, int out_size) {
    const float* ctx     = (const float*)d_in[0];
    const float* tracked = (const float*)d_in[1];
    const float* p0      = (const float*)d_in[2];
    const float* p1      = (const float*)d_in[3];
    const int*   pmask   = (const int*)d_in[4];
    const int*   ckmask  = (const int*)d_in[5];
    const int*   label   = (const int*)d_in[6];
    const int*   ptok    = (const int*)d_in[7];
    const float* W_cqk   = (const float*)d_in[8];
    const float* b_cqk   = (const float*)d_in[9];
    const float* W_k     = (const float*)d_in[10];
    const float* b_k     = (const float*)d_in[11];
    float* out = (float*)d_out;

    k1_fused<<<K1_BLOCKS, 256>>>(ctx, tracked, W_cqk, b_cqk,
                                 p0, p1, pmask, label, ptok, W_k, out);
    k2_v<<<96, 256>>>(W_k, b_k);
    k3_score<<<(NN * KK) / 8, 256>>>(p1, ckmask, out);
}

// round 7
// speedup vs baseline: 2.1742x; 2.1742x over previous
#include <cuda_runtime.h>
#include <cstdint>

// Dims: N=32, K=32, T=128, H=768
#define NN 32
#define KK 32
#define TT 128
#define HH 768
#define H2 1536

// Output layout (float32 concat)
#define OFF_SCORE 0
#define OFF_ENC   1024
#define OFF_MASK  (1024 + 3145728)
#define OFF_USE   (OFF_MASK + 4096)
#define OFF_IDX   (OFF_USE + 24576)

// Scratch
__device__ float g_cqk[NN * HH];   // cqk_pro [n][g] (bias folded)
__device__ float g_v[NN * HH];     // v [n][h]
__device__ float g_c[NN];          // b_k . cqk_pro[n]

// K1 grid layout
#define KA_BLOCKS 384              // 3072 warps: (g=768) x (ngroup=4)
#define PF_BLOCKS 16
#define KD_ITEMS  (786432 + 6144 + 4096 + 4096)   // 800768
#define KD_BLOCKS ((KD_ITEMS + 255) / 256)        // 3128
#define K1_BLOCKS (KA_BLOCKS + PF_BLOCKS + KD_BLOCKS)

// ---------------------------------------------------------------------------
// K1: fused [kA (8-way n-blocked GEMV) | L2 prefetch | gather]
//   kA: warp = (g, ngroup of 8 n). Lanes split the W row (coalesced LDG.128,
//   exactly as R2), 8 accumulators give 8x W reuse. W_cqk L2 traffic: 38 MB.
// ---------------------------------------------------------------------------
__global__ void __launch_bounds__(256) k1_fused(
    const float* __restrict__ ctx,      // (N,3,H)
    const float* __restrict__ tracked,  // (N,H)
    const float* __restrict__ W_cqk,    // (H,2H)
    const float* __restrict__ b_cqk,    // (H,)
    const float* __restrict__ p0,       // (N,K,T,H)
    const float* __restrict__ p1,       // (N,K,H)
    const int*   __restrict__ pmask,    // (N,K,T) bool-as-int32
    const int*   __restrict__ label,    // (N,)
    const int*   __restrict__ ptok,     // (N,K,T)
    const float* __restrict__ W_k,      // (H,H)
    float* __restrict__ out)
{
    int blk = blockIdx.x;
    int tid = threadIdx.x;

    if (blk < KA_BLOCKS) {
        // ---- kA ----
        int gw   = blk * 8 + (tid >> 5);        // 0..3071
        int lane = tid & 31;
        int g    = gw >> 2;
        int n0   = (gw & 3) * 8;

        const float4* W4 = reinterpret_cast<const float4*>(W_cqk + (size_t)g * H2);

        float acc[8];
#pragma unroll
        for (int nn = 0; nn < 8; ++nn) acc[nn] = 0.f;

#pragma unroll
        for (int i = 0; i < 6; ++i) {
            int j = lane + 32 * i;              // 0..191
            float4 w  = W4[j];
            float4 w2 = W4[192 + j];
#pragma unroll
            for (int nn = 0; nn < 8; ++nn) {
                int n = n0 + nn;
                float4 x  = reinterpret_cast<const float4*>(
                    ctx + ((size_t)n * 3 + 2) * HH)[j];
                float4 x2 = reinterpret_cast<const float4*>(
                    tracked + (size_t)n * HH)[j];
                float s = acc[nn];
                s = fmaf(w.x,  x.x,  s); s = fmaf(w.y,  x.y,  s);
                s = fmaf(w.z,  x.z,  s); s = fmaf(w.w,  x.w,  s);
                s = fmaf(w2.x, x2.x, s); s = fmaf(w2.y, x2.y, s);
                s = fmaf(w2.z, x2.z, s); s = fmaf(w2.w, x2.w, s);
                acc[nn] = s;
            }
        }
        float bg = __ldg(b_cqk + g);
#pragma unroll
        for (int nn = 0; nn < 8; ++nn) {
            float s = acc[nn];
#pragma unroll
            for (int o = 16; o > 0; o >>= 1) s += __shfl_down_sync(0xffffffffu, s, o);
            if (lane == 0) g_cqk[(size_t)(n0 + nn) * HH + g] = s + bg;
        }
        return;
    }

    if (blk < KA_BLOCKS + PF_BLOCKS) {
        // ---- L2 prefetch: p1 (3MB) + W_k (2.25MB) for K2/K3 ----
        int pidx = (blk - KA_BLOCKS) * 256 + tid;
        const char* b1 = (const char*)p1;
        const char* b2 = (const char*)W_k;
        for (int i = pidx; i < 24576; i += PF_BLOCKS * 256)
            asm volatile("prefetch.global.L2 [%0];" :: "l"(b1 + (size_t)i * 128));
        for (int i = pidx; i < 18432; i += PF_BLOCKS * 256)
            asm volatile("prefetch.global.L2 [%0];" :: "l"(b2 + (size_t)i * 128));
        return;
    }

    // ---- gather ----
    int idx = (blk - KA_BLOCKS - PF_BLOCKS) * 256 + tid;
    const int ENC_F4 = NN * TT * HH / 4;        // 786432
    const int USE_F4 = NN * HH / 4;             // 6144
    const int MT     = NN * TT;                 // 4096

    if (idx < ENC_F4) {
        int per_n = TT * HH / 4;                // 24576
        int n = idx / per_n;
        int r = idx - n * per_n;
        int lab = __ldg(label + n);
        const float4* src = reinterpret_cast<const float4*>(
            p0 + ((size_t)(n * KK + lab)) * TT * HH);
        float4* dst = reinterpret_cast<float4*>(out + OFF_ENC + (size_t)n * TT * HH);
        dst[r] = src[r];
        return;
    }
    idx -= ENC_F4;
    if (idx < USE_F4) {
        int per_n = HH / 4;                     // 192
        int n = idx / per_n;
        int r = idx - n * per_n;
        int lab = __ldg(label + n);
        const float4* src = reinterpret_cast<const float4*>(
            p1 + ((size_t)(n * KK + lab)) * HH);
        float4* dst = reinterpret_cast<float4*>(out + OFF_USE + (size_t)n * HH);
        dst[r] = src[r];
        return;
    }
    idx -= USE_F4;
    if (idx < MT) {
        int n = idx / TT;
        int t = idx - n * TT;
        int lab = __ldg(label + n);
        out[OFF_MASK + idx] = (pmask[((size_t)(n * KK + lab)) * TT + t] != 0) ? 1.0f : 0.0f;
        return;
    }
    idx -= MT;
    if (idx < MT) {
        int n = idx / TT;
        int t = idx - n * TT;
        int lab = __ldg(label + n);
        out[OFF_IDX + idx] = (float)ptok[((size_t)(n * KK + lab)) * TT + t];
        return;
    }
}

// ---------------------------------------------------------------------------
// K2: v[n,h] = sum_g cqk[n,g] * W_k[g,h]  (8-way n-blocked)
//   Grid 96+1 blocks x 128 thr. Block (ht, ngrp): h-tile of 32, n-group of 8.
//   Thread: h = tid&31 (coalesced W_k LDG), gsub = tid>>5 splits g 4-way.
//   cqk staged in smem [g][nn] (uniform broadcast reads). Block 96 computes c.
// ---------------------------------------------------------------------------
__global__ void __launch_bounds__(128) k2_v(
    const float* __restrict__ W_k,   // (H,H)
    const float* __restrict__ b_k)   // (H,)
{
    __shared__ float sc[HH * 9];                // [g][nn] stride 9 (27.6KB)
    __shared__ float red[4 * 32 * 9];           // [gsub][hl][nn] stride 9

    int blk = blockIdx.x;
    int tid = threadIdx.x;

    if (blk < 96) {
        int ht   = blk % 24;
        int ngrp = blk / 24;
        int n0   = ngrp * 8;
        int h0   = ht * 32;
        int hl   = tid & 31;
        int gsub = tid >> 5;                    // 0..3

        // stage cqk[n0..n0+7][:] into sc (coalesced over g)
        for (int s = tid; s < 8 * HH; s += 128) {
            int nn = s / HH;
            int g  = s - nn * HH;
            sc[g * 9 + nn] = g_cqk[(size_t)(n0 + nn) * HH + g];
        }
        __syncthreads();

        float acc[8];
#pragma unroll
        for (int nn = 0; nn < 8; ++nn) acc[nn] = 0.f;

        int gbase = gsub * 192;
#pragma unroll 8
        for (int i = 0; i < 192; ++i) {
            int g = gbase + i;
            float wv = __ldg(W_k + (size_t)g * HH + h0 + hl);
#pragma unroll
            for (int nn = 0; nn < 8; ++nn)
                acc[nn] = fmaf(wv, sc[g * 9 + nn], acc[nn]);
        }

#pragma unroll
        for (int nn = 0; nn < 8; ++nn) red[(gsub * 32 + hl) * 9 + nn] = acc[nn];
        __syncthreads();

        // 256 outputs (32 h x 8 n), 128 threads -> 2 each
        for (int o = tid; o < 256; o += 128) {
            int ohl = o >> 3;
            int onn = o & 7;
            float s = red[(0 * 32 + ohl) * 9 + onn] + red[(1 * 32 + ohl) * 9 + onn]
                    + red[(2 * 32 + ohl) * 9 + onn] + red[(3 * 32 + ohl) * 9 + onn];
            g_v[(size_t)(n0 + onn) * HH + h0 + ohl] = s;
        }
        return;
    }

    // ---- c[n] = b_k . cqk[n,:]  (block 96) ----
    __shared__ float cred[32 * 5];
    int n = tid >> 2;
    int q = tid & 3;
    float s = 0.f;
    for (int i = 0; i < 192; ++i) {
        int g = q * 192 + i;
        s = fmaf(__ldg(b_k + g), g_cqk[(size_t)n * HH + g], s);
    }
    cred[n * 5 + q] = s;
    __syncthreads();
    if (tid < 32)
        g_c[tid] = cred[tid * 5 + 0] + cred[tid * 5 + 1]
                 + cred[tid * 5 + 2] + cred[tid * 5 + 3];
}

// ---------------------------------------------------------------------------
// K3: score[n,k] = p1[n,k,:].v[n,:] + c[n], masked. Warp per (n,k).
// p1 L2-resident from K1's prefetch.
// ---------------------------------------------------------------------------
__global__ void __launch_bounds__(256) k3_score(
    const float* __restrict__ p1,        // (N,K,H)
    const int* __restrict__ ck_mask,     // (N,K) bool-as-int32
    float* __restrict__ out)
{
    int wid  = blockIdx.x * 8 + (threadIdx.x >> 5);
    int lane = threadIdx.x & 31;
    int n = wid / KK;
    int k = wid - n * KK;

    const float4* p4 = reinterpret_cast<const float4*>(p1 + ((size_t)n * KK + k) * HH);
    const float4* v4 = reinterpret_cast<const float4*>(g_v + (size_t)n * HH);

    float s = 0.f;
#pragma unroll
    for (int j = lane; j < 192; j += 32) {
        float4 a = p4[j];
        float4 b = v4[j];
        s = fmaf(a.x, b.x, s); s = fmaf(a.y, b.y, s);
        s = fmaf(a.z, b.z, s); s = fmaf(a.w, b.w, s);
    }
#pragma unroll
    for (int o = 16; o > 0; o >>= 1) s += __shfl_down_sync(0xffffffffu, s, o);
    if (lane == 0) {
        s += g_c[n];
        if (ck_mask[n * KK + k] == 0) s = -1e20f;
        out[OFF_SCORE + n * KK + k] = s;
    }
}

extern "C" void kernel_launch(void* const* d_in, const int* in_sizes, int n_in,
                              void* d_out, int out_size) {
    const float* ctx     = (const float*)d_in[0];
    const float* tracked = (const float*)d_in[1];
    const float* p0      = (const float*)d_in[2];
    const float* p1      = (const float*)d_in[3];
    const int*   pmask   = (const int*)d_in[4];
    const int*   ckmask  = (const int*)d_in[5];
    const int*   label   = (const int*)d_in[6];
    const int*   ptok    = (const int*)d_in[7];
    const float* W_cqk   = (const float*)d_in[8];
    const float* b_cqk   = (const float*)d_in[9];
    const float* W_k     = (const float*)d_in[10];
    const float* b_k     = (const float*)d_in[11];
    float* out = (float*)d_out;

    k1_fused<<<K1_BLOCKS, 256>>>(ctx, tracked, W_cqk, b_cqk,
                                 p0, p1, pmask, label, ptok, W_k, out);
    k2_v<<<97, 128>>>(W_k, b_k);
    k3_score<<<(NN * KK) / 8, 256>>>(p1, ckmask, out);
}